// round 6
// baseline (speedup 1.0000x reference)
#include <cuda_runtime.h>

// SNN XOR net — eligibility + wave-count round.
// Body bit-identical to R4/R5 (FSET spike, 2 elem/thread, 32 regs).
// Launch shape: block=256 + 30KB smem ballast -> 7 blocks/SM (smem-capped)
// = 56 warps/SM (14/SMSP eligible, vs 7 before) for issue slack, and
// grid=2048 -> 1.98 waves (one transition instead of three) at 98.9% fill.

#define T_STEPS 20
#define BETA 0.9f
#define THR 1.0f

__device__ __forceinline__ float fset_gt(float a, float b) {
    float d;
    asm("set.gt.f32.f32 %0, %1, %2;" : "=f"(d) : "f"(a), "f"(b));
    return d;  // 1.0f if a > b else 0.0f
}

__global__ void __launch_bounds__(256) snn_xornet_kernel(
    const float* __restrict__ x,    // [B,2]
    const float* __restrict__ w1,   // [4,2]
    const float* __restrict__ w2,   // [1,4]
    float* __restrict__ out,        // [T,B]
    int B)
{
    const int i = blockIdx.x * blockDim.x + threadIdx.x;  // group of 2 elems
    if (i * 2 >= B) return;

    float w1r[4][2];
#pragma unroll
    for (int h = 0; h < 4; h++) {
        w1r[h][0] = __ldg(&w1[2 * h + 0]);
        w1r[h][1] = __ldg(&w1[2 * h + 1]);
    }
    float w2r[4];
#pragma unroll
    for (int h = 0; h < 4; h++) w2r[h] = __ldg(&w2[h]);

    // x for 2 batch elements: 4 contiguous floats
    const float4 xv = reinterpret_cast<const float4*>(x)[i];
    const float xs[2][2] = {{xv.x, xv.y}, {xv.z, xv.w}};

    // cur = x @ w1^T (identical rounding to previous passing kernels)
    float cur[2][4];
#pragma unroll
    for (int j = 0; j < 2; j++)
#pragma unroll
        for (int h = 0; h < 4; h++)
            cur[j][h] = fmaf(xs[j][0], w1r[h][0], xs[j][1] * w1r[h][1]);

    // State: membranes + spos (1.0 if spiked last step else 0.0)
    float m1[2][4], s1[2][4];
    float m2[2], s2[2];
#pragma unroll
    for (int j = 0; j < 2; j++) {
        m2[j] = 0.0f; s2[j] = 0.0f;
#pragma unroll
        for (int h = 0; h < 4; h++) { m1[j][h] = 0.0f; s1[j][h] = 0.0f; }
    }

    float2* out2 = reinterpret_cast<float2*>(out);
    const int Bh = B >> 1;

#pragma unroll
    for (int t = 0; t < T_STEPS; t++) {
        float2 v;
#pragma unroll
        for (int j = 0; j < 2; j++) {
            float acc = 0.0f;
#pragma unroll
            for (int h = 0; h < 4; h++) {
                float m = fmaf(BETA, m1[j][h], cur[j][h]) - s1[j][h];
                m1[j][h] = m;
                const float sp = fset_gt(m, THR);        // FSET: 1.0/0.0
                s1[j][h] = sp;
                acc = fmaf(sp, w2r[h], acc);             // exact: +w2 or +0
            }
            const float mo = fmaf(BETA, m2[j], acc) - s2[j];
            m2[j] = mo;
            const float so = fset_gt(mo, THR);
            s2[j] = so;
            if (j == 0) v.x = so; else v.y = so;
        }
        out2[(size_t)t * Bh + i] = v;
    }
}

extern "C" void kernel_launch(void* const* d_in, const int* in_sizes, int n_in,
                              void* d_out, int out_size) {
    const float* x  = (const float*)d_in[0];   // [B,2]
    const float* w1 = (const float*)d_in[1];   // [4,2]
    const float* w2 = (const float*)d_in[2];   // [1,4]
    float* out = (float*)d_out;                // [T,B,1]

    const int B = in_sizes[0] / 2;
    const int groups = B / 2;
    const int threads = 256;
    const int blocks = (groups + threads - 1) / threads;
    const size_t ballast = 30 * 1024;  // smem cap -> 7 blocks/SM (56 warps/SM)
    snn_xornet_kernel<<<blocks, threads, ballast>>>(x, w1, w2, out, B);
}

// round 7
// speedup vs baseline: 1.0184x; 1.0184x over previous
#include <cuda_runtime.h>

// SNN XOR net — store-width + FFMA-imm round.
// Body arithmetic bit-identical to R4-R6 (FSET spike 1.0/0.0; same op order):
//   m   = fma(beta,m,cur); m = fma(s_prev, -1, m)   [== m - s_prev exactly]
//   s   = FSET(m > 1)
//   acc = fma(s, w2[h], acc)  in h order
//   mo  = fma(beta,m2,acc); mo = fma(s2,-1,mo); s2 = FSET; o = s2
// Changes: 4 elems/thread -> one STG.128 per timestep (3.0 issue-cyc/elem vs
// 3.88 for STG.64, half the addressing); reset FADD -> FFMA-imm (rt 1, bit-exact).
// block=128 + 30KB ballast pins 7 blocks/SM; grid=2048 -> 1.98 waves, 98.9% fill.

#define T_STEPS 20
#define BETA 0.9f
#define THR 1.0f

__device__ __forceinline__ float fset_gt(float a, float b) {
    float d;
    asm("set.gt.f32.f32 %0, %1, %2;" : "=f"(d) : "f"(a), "f"(b));
    return d;  // 1.0f if a > b else 0.0f
}

__global__ void __launch_bounds__(128) snn_xornet_kernel(
    const float* __restrict__ x,    // [B,2]
    const float* __restrict__ w1,   // [4,2]
    const float* __restrict__ w2,   // [1,4]
    float* __restrict__ out,        // [T,B]
    int B)
{
    extern __shared__ float smem_ballast[];   // occupancy ballast, never used
    const int i = blockIdx.x * blockDim.x + threadIdx.x;  // group of 4 elems
    if (i * 4 >= B) return;
    if (B < 0) smem_ballast[threadIdx.x] = (float)i;  // never executes

    float w1r[4][2];
#pragma unroll
    for (int h = 0; h < 4; h++) {
        w1r[h][0] = __ldg(&w1[2 * h + 0]);
        w1r[h][1] = __ldg(&w1[2 * h + 1]);
    }
    float w2r[4];
#pragma unroll
    for (int h = 0; h < 4; h++) w2r[h] = __ldg(&w2[h]);

    // x for 4 batch elements: 8 contiguous floats
    const float4 xa = reinterpret_cast<const float4*>(x)[2 * i + 0];
    const float4 xb = reinterpret_cast<const float4*>(x)[2 * i + 1];
    const float xs[4][2] = {{xa.x, xa.y}, {xa.z, xa.w}, {xb.x, xb.y}, {xb.z, xb.w}};

    // cur = x @ w1^T (identical rounding to all passing kernels)
    float cur[4][4];
#pragma unroll
    for (int j = 0; j < 4; j++)
#pragma unroll
        for (int h = 0; h < 4; h++)
            cur[j][h] = fmaf(xs[j][0], w1r[h][0], xs[j][1] * w1r[h][1]);

    float m1[4][4], s1[4][4];
    float m2[4], s2[4];
#pragma unroll
    for (int j = 0; j < 4; j++) {
        m2[j] = 0.0f; s2[j] = 0.0f;
#pragma unroll
        for (int h = 0; h < 4; h++) { m1[j][h] = 0.0f; s1[j][h] = 0.0f; }
    }

    float4* out4 = reinterpret_cast<float4*>(out);
    const int Bq = B >> 2;

#pragma unroll
    for (int t = 0; t < T_STEPS; t++) {
        float o[4];
#pragma unroll
        for (int j = 0; j < 4; j++) {
            float acc = 0.0f;
#pragma unroll
            for (int h = 0; h < 4; h++) {
                float m = fmaf(BETA, m1[j][h], cur[j][h]);
                m = fmaf(s1[j][h], -1.0f, m);        // == m - s  (bit-exact), FFMA-imm
                m1[j][h] = m;
                const float sp = fset_gt(m, THR);    // FSET: 1.0/0.0
                s1[j][h] = sp;
                acc = fmaf(sp, w2r[h], acc);         // exact: +w2 or +0
            }
            float mo = fmaf(BETA, m2[j], acc);
            mo = fmaf(s2[j], -1.0f, mo);             // == mo - s2 (bit-exact)
            m2[j] = mo;
            const float so = fset_gt(mo, THR);
            s2[j] = so;
            o[j] = so;
        }
        float4 v;
        v.x = o[0]; v.y = o[1]; v.z = o[2]; v.w = o[3];
        out4[(size_t)t * Bq + i] = v;
    }
}

extern "C" void kernel_launch(void* const* d_in, const int* in_sizes, int n_in,
                              void* d_out, int out_size) {
    const float* x  = (const float*)d_in[0];   // [B,2]
    const float* w1 = (const float*)d_in[1];   // [4,2]
    const float* w2 = (const float*)d_in[2];   // [1,4]
    float* out = (float*)d_out;                // [T,B,1]

    const int B = in_sizes[0] / 2;
    const int groups = B / 4;
    const int threads = 128;
    const int blocks = (groups + threads - 1) / threads;   // 2048
    const size_t ballast = 30 * 1024;  // 7 blocks/SM -> wave=1036, 1.98 waves
    snn_xornet_kernel<<<blocks, threads, ballast>>>(x, w1, w2, out, B);
}